// round 1
// baseline (speedup 1.0000x reference)
#include <cuda_runtime.h>
#include <float.h>
#include <math.h>

// Problem constants
#define E    256
#define C    128
#define HW   3136          // 56*56
#define NC   200
#define NP   512
#define NL   64
#define LL   8
#define ED   256           // EDGE_DIM = 2C
#define LIN  258           // LOOP_IN
#define FEAT 64

// Output layout (flattened concat of reference return tuple)
#define OFF_OUT 0
#define OFF_EC  (E*C)            // 32768
#define OFF_LC  (OFF_EC + E)     // 33024
#define OFF_LE  (OFF_LC + NL)    // 33088  (+ NL*E = 16384 -> 49472 total)

// Device scratch (no allocation allowed)
__device__ float g_edge_x[E*ED];
__device__ float g_corner_feat[NC*ED];
__device__ float g_loop_feat[NL*FEAT];

// ---------------------------------------------------------------------------
// Kernel 1: per-(edge,channel) global max pool over 56x56 + build edge_x rows
// Dominant cost: 411 MB HBM read. float4 loads, block tree-reduce.
// ---------------------------------------------------------------------------
__global__ void k_maxpool(const float* __restrict__ img,
                          const float* __restrict__ coord) {
    int ec = blockIdx.x;                       // e*C + c
    const float4* p = (const float4*)img + (size_t)ec * (HW / 4);
    float m = -FLT_MAX;
    for (int i = threadIdx.x; i < HW / 4; i += blockDim.x) {
        float4 v = p[i];
        m = fmaxf(m, fmaxf(fmaxf(v.x, v.y), fmaxf(v.z, v.w)));
    }
    // warp reduce
    #pragma unroll
    for (int off = 16; off > 0; off >>= 1)
        m = fmaxf(m, __shfl_xor_sync(0xFFFFFFFFu, m, off));
    __shared__ float s[8];
    int lane = threadIdx.x & 31, wid = threadIdx.x >> 5;
    if (lane == 0) s[wid] = m;
    __syncthreads();
    if (threadIdx.x == 0) {
        float mm = s[0];
        #pragma unroll
        for (int w = 1; w < 8; w++) mm = fmaxf(mm, s[w]);
        int e = ec >> 7, c = ec & 127;
        g_edge_x[e * ED + c]     = mm;
        g_edge_x[e * ED + C + c] = coord[ec];
    }
}

// ---------------------------------------------------------------------------
// Kernel 2: edge confidence MLP: relu(edge_x @ W1^T + b1) @ W2^T + b2, sigmoid
// ---------------------------------------------------------------------------
__global__ void k_edgeconf(const float* __restrict__ W1, const float* __restrict__ b1,
                           const float* __restrict__ W2, const float* __restrict__ b2,
                           float* __restrict__ out) {
    int e = blockIdx.x, t = threadIdx.x;       // 64 threads
    __shared__ float sx[ED];
    for (int i = t; i < ED; i += 64) sx[i] = g_edge_x[e * ED + i];
    __syncthreads();
    float acc = b1[t];
    #pragma unroll 4
    for (int i = 0; i < ED; i++) acc += sx[i] * W1[t * ED + i];
    __shared__ float sr[64];
    sr[t] = fmaxf(acc, 0.f) * W2[t];
    __syncthreads();
    for (int s = 32; s > 0; s >>= 1) {
        if (t < s) sr[t] += sr[t + s];
        __syncthreads();
    }
    if (t == 0) out[OFF_EC + e] = 1.f / (1.f + expf(-(sr[0] + b2[0])));
}

// ---------------------------------------------------------------------------
// Kernel 3: deterministic scatter-mean of edge_x onto corners
// One block per corner scans all NP pairs (tiny, deterministic — no atomics).
// ---------------------------------------------------------------------------
__global__ void k_cornerfeat(const int* __restrict__ pairs) {
    int c = blockIdx.x, t = threadIdx.x;       // 256 threads = feature dim
    float sum = 0.f, cnt = 0.f;
    for (int p = 0; p < NP; p++) {
        int pc = pairs[2 * p];
        if (pc == c) {
            sum += g_edge_x[pairs[2 * p + 1] * ED + t];
            cnt += 1.f;
        }
    }
    g_corner_feat[c * ED + t] = sum / fmaxf(cnt, 1.f);
}

// ---------------------------------------------------------------------------
// Kernel 4: LoopEncoder (3x reflect-pad conv1d k=3 + ReLU, max over L) + conf MLP
// One block per loop, 512 threads: thread = (out_channel o, position j).
// ---------------------------------------------------------------------------
__global__ void k_loopenc(const int* __restrict__ loops, const float* __restrict__ corners,
                          const float* __restrict__ Wc0, const float* __restrict__ bc0,
                          const float* __restrict__ Wc1, const float* __restrict__ bc1,
                          const float* __restrict__ Wc2, const float* __restrict__ bc2,
                          const float* __restrict__ Wl1, const float* __restrict__ bl1,
                          const float* __restrict__ Wl2, const float* __restrict__ bl2,
                          float* __restrict__ out) {
    int l = blockIdx.x, t = threadIdx.x;
    __shared__ float x0[LIN * LL];             // 258 x 8, channel-major
    __shared__ float hA[64 * LL], hB[64 * LL];
    __shared__ int   ci[LL];
    if (t < LL) ci[t] = loops[l * LL + t];
    __syncthreads();
    for (int idx = t; idx < LIN * LL; idx += 512) {
        int i = idx >> 3, j = idx & 7;
        float v = (i < ED) ? g_corner_feat[ci[j] * ED + i]
                           : corners[ci[j] * 2 + (i - ED)];
        x0[idx] = v;
    }
    __syncthreads();

    int o = t >> 3, j = t & 7;
    int jm = j - 1; if (jm < 0) jm = 1;        // ReflectionPad1d(1)
    int jp = j + 1; if (jp > 7) jp = 6;

    // conv0: 258 -> 64
    float acc = bc0[o];
    {
        const float* w = Wc0 + o * LIN * 3;
        for (int i = 0; i < LIN; i++) {
            const float* xr = &x0[i * LL];
            acc += w[3*i] * xr[jm] + w[3*i+1] * xr[j] + w[3*i+2] * xr[jp];
        }
    }
    hA[o * LL + j] = fmaxf(acc, 0.f);
    __syncthreads();

    // conv1: 64 -> 64
    acc = bc1[o];
    {
        const float* w = Wc1 + o * 64 * 3;
        #pragma unroll 8
        for (int i = 0; i < 64; i++) {
            const float* xr = &hA[i * LL];
            acc += w[3*i] * xr[jm] + w[3*i+1] * xr[j] + w[3*i+2] * xr[jp];
        }
    }
    hB[o * LL + j] = fmaxf(acc, 0.f);
    __syncthreads();

    // conv2: 64 -> 64
    acc = bc2[o];
    {
        const float* w = Wc2 + o * 64 * 3;
        #pragma unroll 8
        for (int i = 0; i < 64; i++) {
            const float* xr = &hB[i * LL];
            acc += w[3*i] * xr[jm] + w[3*i+1] * xr[j] + w[3*i+2] * xr[jp];
        }
    }
    hA[o * LL + j] = fmaxf(acc, 0.f);
    __syncthreads();

    __shared__ float lf[64];
    if (j == 0) {
        float m = -FLT_MAX;
        #pragma unroll
        for (int k = 0; k < LL; k++) m = fmaxf(m, hA[o * LL + k]);
        lf[o] = m;
        g_loop_feat[l * FEAT + o] = m;
    }
    __syncthreads();

    __shared__ float gg[32];
    if (t < 32) {
        float a = bl1[t];
        #pragma unroll 8
        for (int i = 0; i < 64; i++) a += lf[i] * Wl1[t * 64 + i];
        gg[t] = fmaxf(a, 0.f) * Wl2[t];
    }
    __syncthreads();
    if (t == 0) {
        float s = bl2[0];
        #pragma unroll
        for (int i = 0; i < 32; i++) s += gg[i];
        out[OFF_LC + l] = 1.f / (1.f + expf(-s));
    }
}

// ---------------------------------------------------------------------------
// Kernel 5: loop-edge incidence. edge (a,b) in loop iff (a,b) == some
// (c_j, c_{j-1}) or (c_j, c_{j+1}) pair (exact ordered match per reference).
// ---------------------------------------------------------------------------
__global__ void k_loopedges(const int* __restrict__ loops,
                            const int* __restrict__ edge_corner,
                            float* __restrict__ out) {
    int l = blockIdx.x, e = threadIdx.x;       // 256 threads = edges
    __shared__ int ci[LL];
    if (e < LL) ci[e] = loops[l * LL + e];
    __syncthreads();
    int a = edge_corner[2 * e], b = edge_corner[2 * e + 1];
    float r = 0.f;
    #pragma unroll
    for (int j = 0; j < LL; j++) {
        int cj = ci[j];
        int cp = ci[(j + LL - 1) & 7];
        int cn = ci[(j + 1) & 7];
        if (cj == a && (cp == b || cn == b)) r = 1.f;
    }
    out[OFF_LE + l * E + e] = r;
}

// ---------------------------------------------------------------------------
// Kernel 6: confidence-weighted loop-feature average per edge + final 1x1 conv
// ---------------------------------------------------------------------------
__global__ void k_final(const float* __restrict__ coord,
                        const float* __restrict__ Wagg,
                        float* __restrict__ out) {
    int e = blockIdx.x, t = threadIdx.x;       // 128 threads
    __shared__ float cat[C + FEAT];            // 192
    __shared__ float lconf[NL];
    if (t < NL) lconf[t] = out[OFF_LC + t];
    if (t < C)  cat[t]   = coord[e * C + t];
    __syncthreads();
    if (t < FEAT) {
        float num = 0.f, den = 0.f;
        #pragma unroll 8
        for (int l = 0; l < NL; l++) {
            float w = lconf[l] * out[OFF_LE + l * E + e];
            num += w * g_loop_feat[l * FEAT + t];
            den += w;
        }
        cat[C + t] = num / fmaxf(den, 1e-4f);
    }
    __syncthreads();
    float acc = 0.f;
    const float* w = Wagg + t * (C + FEAT);
    #pragma unroll 8
    for (int i = 0; i < C + FEAT; i++) acc += cat[i] * w[i];
    out[e * C + t] = fmaxf(acc, 0.f);
}

// ---------------------------------------------------------------------------
extern "C" void kernel_launch(void* const* d_in, const int* in_sizes, int n_in,
                              void* d_out, int out_size) {
    const float* image_x = (const float*)d_in[0];
    const float* coord_x = (const float*)d_in[1];
    const float* corners = (const float*)d_in[2];
    const int*   pairs   = (const int*)  d_in[3];
    const int*   e_crn   = (const int*)  d_in[4];
    const int*   loops   = (const int*)  d_in[5];
    const float* W_ep1 = (const float*)d_in[6];
    const float* b_ep1 = (const float*)d_in[7];
    const float* W_ep2 = (const float*)d_in[8];
    const float* b_ep2 = (const float*)d_in[9];
    const float* Wc0 = (const float*)d_in[10];
    const float* bc0 = (const float*)d_in[11];
    const float* Wc1 = (const float*)d_in[12];
    const float* bc1 = (const float*)d_in[13];
    const float* Wc2 = (const float*)d_in[14];
    const float* bc2 = (const float*)d_in[15];
    const float* Wl1 = (const float*)d_in[16];
    const float* bl1 = (const float*)d_in[17];
    const float* Wl2 = (const float*)d_in[18];
    const float* bl2 = (const float*)d_in[19];
    const float* Wagg = (const float*)d_in[20];
    float* out = (float*)d_out;

    k_maxpool   <<<E * C, 256>>>(image_x, coord_x);
    k_edgeconf  <<<E, 64>>>(W_ep1, b_ep1, W_ep2, b_ep2, out);
    k_cornerfeat<<<NC, 256>>>(pairs);
    k_loopenc   <<<NL, 512>>>(loops, corners, Wc0, bc0, Wc1, bc1, Wc2, bc2,
                              Wl1, bl1, Wl2, bl2, out);
    k_loopedges <<<NL, 256>>>(loops, e_crn, out);
    k_final     <<<E, 128>>>(coord_x, Wagg, out);
}

// round 2
// speedup vs baseline: 1.1749x; 1.1749x over previous
#include <cuda_runtime.h>
#include <float.h>
#include <math.h>

// Problem constants
#define E    256
#define C    128
#define HW   3136          // 56*56
#define NC   200
#define NP   512
#define NL   64
#define LL   8
#define ED   256           // EDGE_DIM = 2C
#define LIN  258           // LOOP_IN
#define FEAT 64

// Output layout (flattened concat of reference return tuple)
#define OFF_OUT 0
#define OFF_EC  (E*C)            // 32768
#define OFF_LC  (OFF_EC + E)     // 33024
#define OFF_LE  (OFF_LC + NL)    // 33088  (+ NL*E = 16384 -> 49472 total)

// Device scratch (no allocation allowed)
__device__ float g_edge_x[E*ED];
__device__ float g_corner_feat[NC*ED];
__device__ float g_loop_feat[NL*FEAT];
__device__ float g_h1[NL*64*LL];   // conv0 output, layout [l][o][j]

// ---------------------------------------------------------------------------
// Kernel 1: per-(edge,channel) global max pool over 56x56 + build edge_x rows
// Dominant cost: 411 MB HBM read. float4 loads, block tree-reduce.
// ---------------------------------------------------------------------------
__global__ void k_maxpool(const float* __restrict__ img,
                          const float* __restrict__ coord) {
    int ec = blockIdx.x;                       // e*C + c
    const float4* p = (const float4*)img + (size_t)ec * (HW / 4);
    float m = -FLT_MAX;
    #pragma unroll 4
    for (int i = threadIdx.x; i < HW / 4; i += blockDim.x) {
        float4 v = p[i];
        m = fmaxf(m, fmaxf(fmaxf(v.x, v.y), fmaxf(v.z, v.w)));
    }
    #pragma unroll
    for (int off = 16; off > 0; off >>= 1)
        m = fmaxf(m, __shfl_xor_sync(0xFFFFFFFFu, m, off));
    __shared__ float s[8];
    int lane = threadIdx.x & 31, wid = threadIdx.x >> 5;
    if (lane == 0) s[wid] = m;
    __syncthreads();
    if (threadIdx.x == 0) {
        float mm = s[0];
        #pragma unroll
        for (int w = 1; w < 8; w++) mm = fmaxf(mm, s[w]);
        int e = ec >> 7, c = ec & 127;
        g_edge_x[e * ED + c]     = mm;
        g_edge_x[e * ED + C + c] = coord[ec];
    }
}

// ---------------------------------------------------------------------------
// Kernel 2: edge confidence MLP
// ---------------------------------------------------------------------------
__global__ void k_edgeconf(const float* __restrict__ W1, const float* __restrict__ b1,
                           const float* __restrict__ W2, const float* __restrict__ b2,
                           float* __restrict__ out) {
    int e = blockIdx.x, t = threadIdx.x;       // 64 threads
    __shared__ float sx[ED];
    for (int i = t; i < ED; i += 64) sx[i] = g_edge_x[e * ED + i];
    __syncthreads();
    float acc = b1[t];
    #pragma unroll 8
    for (int i = 0; i < ED; i++) acc += sx[i] * W1[t * ED + i];
    __shared__ float sr[64];
    sr[t] = fmaxf(acc, 0.f) * W2[t];
    __syncthreads();
    for (int s = 32; s > 0; s >>= 1) {
        if (t < s) sr[t] += sr[t + s];
        __syncthreads();
    }
    if (t == 0) out[OFF_EC + e] = 1.f / (1.f + expf(-(sr[0] + b2[0])));
}

// ---------------------------------------------------------------------------
// Kernel 3: deterministic scatter-mean of edge_x onto corners.
// Pairs staged in shared once; one block per corner, thread = feature channel.
// ---------------------------------------------------------------------------
__global__ void k_cornerfeat(const int* __restrict__ pairs) {
    int c = blockIdx.x, t = threadIdx.x;       // 256 threads
    __shared__ int sp[NP * 2];
    for (int i = t; i < NP * 2; i += 256) sp[i] = pairs[i];
    __syncthreads();
    float sum = 0.f, cnt = 0.f;
    #pragma unroll 4
    for (int p = 0; p < NP; p++) {
        if (sp[2 * p] == c) {
            sum += g_edge_x[sp[2 * p + 1] * ED + t];
            cnt += 1.f;
        }
    }
    g_corner_feat[c * ED + t] = sum / fmaxf(cnt, 1.f);
}

// ---------------------------------------------------------------------------
// Kernel 4a: conv0 (258 -> 64, k=3, reflect pad) — the big conv.
// grid = (8 o-groups, NL loops); 256 threads = (o_local:8, j:8, ks:4).
// 4-way K-split per output with shfl reduction -> 512 blocks fill the chip.
// ---------------------------------------------------------------------------
__global__ void k_conv0(const int* __restrict__ loops, const float* __restrict__ corners,
                        const float* __restrict__ Wc0, const float* __restrict__ bc0) {
    int l = blockIdx.y;
    int t = threadIdx.x;
    int ks = t & 3;
    int grp = t >> 2;                 // 0..63 = o_local*8 + j
    int o_local = grp >> 3, j = grp & 7;
    int o = blockIdx.x * 8 + o_local;

    __shared__ int   ci[LL];
    __shared__ float x0[LIN * LL];    // [i][j]
    if (t < LL) ci[t] = loops[l * LL + t];
    __syncthreads();
    for (int idx = t; idx < LIN * LL; idx += 256) {
        int i = idx >> 3, jj = idx & 7;
        x0[idx] = (i < ED) ? g_corner_feat[ci[jj] * ED + i]
                           : corners[ci[jj] * 2 + (i - ED)];
    }
    __syncthreads();

    int jm = j - 1; if (jm < 0) jm = 1;
    int jp = j + 1; if (jp > 7) jp = 6;

    float acc = 0.f;
    #pragma unroll 8
    for (int i = ks; i < LIN; i += 4) {
        const float* w = Wc0 + (o * LIN + i) * 3;
        acc += w[0] * x0[i * 8 + jm] + w[1] * x0[i * 8 + j] + w[2] * x0[i * 8 + jp];
    }
    // reduce over the 4 ks lanes (consecutive lanes in a warp)
    acc += __shfl_down_sync(0xFFFFFFFFu, acc, 1);
    acc += __shfl_down_sync(0xFFFFFFFFu, acc, 2);
    if (ks == 0)
        g_h1[(l * 64 + o) * LL + j] = fmaxf(acc + bc0[o], 0.f);
}

// ---------------------------------------------------------------------------
// Kernel 4b: conv1 + conv2 + max over L + loop-conf MLP (small work).
// grid = NL, 512 threads = (o:64, j:8).
// ---------------------------------------------------------------------------
__global__ void k_looprest(const float* __restrict__ Wc1, const float* __restrict__ bc1,
                           const float* __restrict__ Wc2, const float* __restrict__ bc2,
                           const float* __restrict__ Wl1, const float* __restrict__ bl1,
                           const float* __restrict__ Wl2, const float* __restrict__ bl2,
                           float* __restrict__ out) {
    int l = blockIdx.x, t = threadIdx.x;
    int o = t >> 3, j = t & 7;
    __shared__ float hA[64 * LL], hB[64 * LL];
    hA[t] = g_h1[l * 64 * LL + t];   // [i][j] layout matches
    __syncthreads();

    int jm = j - 1; if (jm < 0) jm = 1;
    int jp = j + 1; if (jp > 7) jp = 6;

    float acc = bc1[o];
    {
        const float* w = Wc1 + o * 64 * 3;
        #pragma unroll 16
        for (int i = 0; i < 64; i++) {
            const float* xr = &hA[i * LL];
            acc += w[3*i] * xr[jm] + w[3*i+1] * xr[j] + w[3*i+2] * xr[jp];
        }
    }
    hB[o * LL + j] = fmaxf(acc, 0.f);
    __syncthreads();

    acc = bc2[o];
    {
        const float* w = Wc2 + o * 64 * 3;
        #pragma unroll 16
        for (int i = 0; i < 64; i++) {
            const float* xr = &hB[i * LL];
            acc += w[3*i] * xr[jm] + w[3*i+1] * xr[j] + w[3*i+2] * xr[jp];
        }
    }
    hA[o * LL + j] = fmaxf(acc, 0.f);
    __syncthreads();

    __shared__ float lf[64];
    if (j == 0) {
        float m = -FLT_MAX;
        #pragma unroll
        for (int k = 0; k < LL; k++) m = fmaxf(m, hA[o * LL + k]);
        lf[o] = m;
        g_loop_feat[l * FEAT + o] = m;
    }
    __syncthreads();

    __shared__ float gg[32];
    if (t < 32) {
        float a = bl1[t];
        #pragma unroll 8
        for (int i = 0; i < 64; i++) a += lf[i] * Wl1[t * 64 + i];
        gg[t] = fmaxf(a, 0.f) * Wl2[t];
    }
    __syncthreads();
    if (t == 0) {
        float s = bl2[0];
        #pragma unroll
        for (int i = 0; i < 32; i++) s += gg[i];
        out[OFF_LC + l] = 1.f / (1.f + expf(-s));
    }
}

// ---------------------------------------------------------------------------
// Kernel 5: loop-edge incidence (input-only; launched first to hide latency)
// ---------------------------------------------------------------------------
__global__ void k_loopedges(const int* __restrict__ loops,
                            const int* __restrict__ edge_corner,
                            float* __restrict__ out) {
    int l = blockIdx.x, e = threadIdx.x;       // 256 threads = edges
    __shared__ int ci[LL];
    if (e < LL) ci[e] = loops[l * LL + e];
    __syncthreads();
    int a = edge_corner[2 * e], b = edge_corner[2 * e + 1];
    float r = 0.f;
    #pragma unroll
    for (int j = 0; j < LL; j++) {
        int cj = ci[j];
        int cp = ci[(j + LL - 1) & 7];
        int cn = ci[(j + 1) & 7];
        if (cj == a && (cp == b || cn == b)) r = 1.f;
    }
    out[OFF_LE + l * E + e] = r;
}

// ---------------------------------------------------------------------------
// Kernel 6: confidence-weighted loop-feature average per edge + final 1x1 conv
// ---------------------------------------------------------------------------
__global__ void k_final(const float* __restrict__ coord,
                        const float* __restrict__ Wagg,
                        float* __restrict__ out) {
    int e = blockIdx.x, t = threadIdx.x;       // 128 threads
    __shared__ float cat[C + FEAT];            // 192
    __shared__ float lconf[NL];
    if (t < NL) lconf[t] = out[OFF_LC + t];
    if (t < C)  cat[t]   = coord[e * C + t];
    __syncthreads();
    if (t < FEAT) {
        float num = 0.f, den = 0.f;
        #pragma unroll 8
        for (int l = 0; l < NL; l++) {
            float w = lconf[l] * out[OFF_LE + l * E + e];
            num += w * g_loop_feat[l * FEAT + t];
            den += w;
        }
        cat[C + t] = num / fmaxf(den, 1e-4f);
    }
    __syncthreads();
    float acc = 0.f;
    const float* w = Wagg + t * (C + FEAT);
    #pragma unroll 8
    for (int i = 0; i < C + FEAT; i++) acc += cat[i] * w[i];
    out[e * C + t] = fmaxf(acc, 0.f);
}

// ---------------------------------------------------------------------------
extern "C" void kernel_launch(void* const* d_in, const int* in_sizes, int n_in,
                              void* d_out, int out_size) {
    const float* image_x = (const float*)d_in[0];
    const float* coord_x = (const float*)d_in[1];
    const float* corners = (const float*)d_in[2];
    const int*   pairs   = (const int*)  d_in[3];
    const int*   e_crn   = (const int*)  d_in[4];
    const int*   loops   = (const int*)  d_in[5];
    const float* W_ep1 = (const float*)d_in[6];
    const float* b_ep1 = (const float*)d_in[7];
    const float* W_ep2 = (const float*)d_in[8];
    const float* b_ep2 = (const float*)d_in[9];
    const float* Wc0 = (const float*)d_in[10];
    const float* bc0 = (const float*)d_in[11];
    const float* Wc1 = (const float*)d_in[12];
    const float* bc1 = (const float*)d_in[13];
    const float* Wc2 = (const float*)d_in[14];
    const float* bc2 = (const float*)d_in[15];
    const float* Wl1 = (const float*)d_in[16];
    const float* bl1 = (const float*)d_in[17];
    const float* Wl2 = (const float*)d_in[18];
    const float* bl2 = (const float*)d_in[19];
    const float* Wagg = (const float*)d_in[20];
    float* out = (float*)d_out;

    k_loopedges <<<NL, 256>>>(loops, e_crn, out);        // input-only, run first
    k_maxpool   <<<E * C, 256>>>(image_x, coord_x);
    k_edgeconf  <<<E, 64>>>(W_ep1, b_ep1, W_ep2, b_ep2, out);
    k_cornerfeat<<<NC, 256>>>(pairs);
    {
        dim3 grid(8, NL);
        k_conv0 <<<grid, 256>>>(loops, corners, Wc0, bc0);
    }
    k_looprest  <<<NL, 512>>>(Wc1, bc1, Wc2, bc2, Wl1, bl1, Wl2, bl2, out);
    k_final     <<<E, 128>>>(coord_x, Wagg, out);
}

// round 3
// speedup vs baseline: 1.3461x; 1.1456x over previous
#include <cuda_runtime.h>
#include <float.h>
#include <math.h>

// Problem constants
#define E    256
#define C    128
#define HW   3136          // 56*56
#define NC   200
#define NP   512
#define NL   64
#define LL   8
#define ED   256           // EDGE_DIM = 2C
#define LIN  258           // LOOP_IN
#define FEAT 64

// Output layout (flattened concat of reference return tuple)
#define OFF_OUT 0
#define OFF_EC  (E*C)            // 32768
#define OFF_LC  (OFF_EC + E)     // 33024
#define OFF_LE  (OFF_LC + NL)    // 33088  (+ NL*E = 16384 -> 49472 total)

// Device scratch (no allocation allowed)
__device__ float g_edge_x[E*ED];
__device__ float g_corner_feat[NC*ED];
__device__ float g_loop_feat[NL*FEAT];
__device__ float g_h1[NL*64*LL];   // conv0 output, layout [l][o][j]

// ---------------------------------------------------------------------------
// Kernel 1: per-(edge,channel) global max pool over 56x56 + build edge_x rows
// Dominant cost: 411 MB HBM read. float4 loads, block tree-reduce.
// ---------------------------------------------------------------------------
__global__ void k_maxpool(const float* __restrict__ img,
                          const float* __restrict__ coord) {
    int ec = blockIdx.x;                       // e*C + c
    const float4* p = (const float4*)img + (size_t)ec * (HW / 4);
    float m = -FLT_MAX;
    #pragma unroll 4
    for (int i = threadIdx.x; i < HW / 4; i += blockDim.x) {
        float4 v = p[i];
        m = fmaxf(m, fmaxf(fmaxf(v.x, v.y), fmaxf(v.z, v.w)));
    }
    #pragma unroll
    for (int off = 16; off > 0; off >>= 1)
        m = fmaxf(m, __shfl_xor_sync(0xFFFFFFFFu, m, off));
    __shared__ float s[8];
    int lane = threadIdx.x & 31, wid = threadIdx.x >> 5;
    if (lane == 0) s[wid] = m;
    __syncthreads();
    if (threadIdx.x == 0) {
        float mm = s[0];
        #pragma unroll
        for (int w = 1; w < 8; w++) mm = fmaxf(mm, s[w]);
        int e = ec >> 7, c = ec & 127;
        g_edge_x[e * ED + c]     = mm;
        g_edge_x[e * ED + C + c] = coord[ec];
    }
}

// ---------------------------------------------------------------------------
// Kernel 2 (fused): blocks [0,E) = edge-conf MLP; blocks [E, E+NC) = corner
// scatter-mean via deterministic 512-bit match bitmask.
// 256 threads everywhere.
// ---------------------------------------------------------------------------
__global__ void k_edge_corner(const float* __restrict__ W1, const float* __restrict__ b1,
                              const float* __restrict__ W2, const float* __restrict__ b2,
                              const int* __restrict__ pairs,
                              float* __restrict__ out) {
    int t = threadIdx.x;
    if (blockIdx.x < E) {
        // ---- edge confidence for edge e ----
        int e = blockIdx.x;
        __shared__ float sx[ED];
        __shared__ float sr[64];
        for (int i = t; i < ED; i += 256) sx[i] = g_edge_x[e * ED + i];
        __syncthreads();
        int ks = t & 3, o = t >> 2;            // 4-way split over input dim
        float acc = 0.f;
        #pragma unroll 16
        for (int i = ks; i < ED; i += 4) acc += sx[i] * W1[o * ED + i];
        acc += __shfl_down_sync(0xFFFFFFFFu, acc, 1);
        acc += __shfl_down_sync(0xFFFFFFFFu, acc, 2);
        if (ks == 0) sr[o] = fmaxf(acc + b1[o], 0.f) * W2[o];
        __syncthreads();
        if (t < 32) {
            float v = sr[t] + sr[t + 32];
            #pragma unroll
            for (int off = 16; off > 0; off >>= 1)
                v += __shfl_xor_sync(0xFFFFFFFFu, v, off);
            if (t == 0) out[OFF_EC + e] = 1.f / (1.f + expf(-(v + b2[0])));
        }
    } else {
        // ---- corner scatter-mean for corner c ----
        int c = blockIdx.x - E;
        __shared__ unsigned mask[NP / 32];     // 16 words
        __shared__ int sedge[NP];
        if (t < NP / 32) mask[t] = 0u;
        __syncthreads();
        // phase 1: each thread tests 2 pairs; bitwise-OR is order-independent
        #pragma unroll
        for (int k = 0; k < 2; k++) {
            int p = t + k * 256;
            int2 pr = ((const int2*)pairs)[p];
            sedge[p] = pr.y;
            if (pr.x == c) atomicOr(&mask[p >> 5], 1u << (p & 31));
        }
        __syncthreads();
        // phase 2: per-channel sum in increasing pair order (deterministic)
        float sum = 0.f, cnt = 0.f;
        #pragma unroll
        for (int w = 0; w < NP / 32; w++) {
            unsigned m = mask[w];
            while (m) {
                int b = __ffs(m) - 1;
                m &= m - 1;
                sum += g_edge_x[sedge[w * 32 + b] * ED + t];
                cnt += 1.f;
            }
        }
        g_corner_feat[c * ED + t] = sum / fmaxf(cnt, 1.f);
    }
}

// ---------------------------------------------------------------------------
// Kernel 4a: conv0 (258 -> 64, k=3, reflect pad) — the big conv.
// grid = (8 o-groups, NL loops); 256 threads = (ks:4, o_local:8, j:8).
// ---------------------------------------------------------------------------
__global__ void k_conv0(const int* __restrict__ loops, const float* __restrict__ corners,
                        const float* __restrict__ Wc0, const float* __restrict__ bc0) {
    int l = blockIdx.y;
    int t = threadIdx.x;
    int ks = t & 3;
    int grp = t >> 2;                 // 0..63 = o_local*8 + j
    int o_local = grp >> 3, j = grp & 7;
    int o = blockIdx.x * 8 + o_local;

    __shared__ int   ci[LL];
    __shared__ float x0[LIN * LL];    // [i][j]
    if (t < LL) ci[t] = loops[l * LL + t];
    __syncthreads();
    for (int idx = t; idx < LIN * LL; idx += 256) {
        int i = idx >> 3, jj = idx & 7;
        x0[idx] = (i < ED) ? g_corner_feat[ci[jj] * ED + i]
                           : corners[ci[jj] * 2 + (i - ED)];
    }
    __syncthreads();

    int jm = j - 1; if (jm < 0) jm = 1;
    int jp = j + 1; if (jp > 7) jp = 6;

    float acc = 0.f;
    #pragma unroll 8
    for (int i = ks; i < LIN; i += 4) {
        const float* w = Wc0 + (o * LIN + i) * 3;
        acc += w[0] * x0[i * 8 + jm] + w[1] * x0[i * 8 + j] + w[2] * x0[i * 8 + jp];
    }
    acc += __shfl_down_sync(0xFFFFFFFFu, acc, 1);
    acc += __shfl_down_sync(0xFFFFFFFFu, acc, 2);
    if (ks == 0)
        g_h1[(l * 64 + o) * LL + j] = fmaxf(acc + bc0[o], 0.f);
}

// ---------------------------------------------------------------------------
// Kernel 4b: conv1 + conv2 + max over L + loop-conf MLP (small work).
// grid = NL, 512 threads = (o:64, j:8).
// ---------------------------------------------------------------------------
__global__ void k_looprest(const float* __restrict__ Wc1, const float* __restrict__ bc1,
                           const float* __restrict__ Wc2, const float* __restrict__ bc2,
                           const float* __restrict__ Wl1, const float* __restrict__ bl1,
                           const float* __restrict__ Wl2, const float* __restrict__ bl2,
                           float* __restrict__ out) {
    int l = blockIdx.x, t = threadIdx.x;
    int o = t >> 3, j = t & 7;
    __shared__ float hA[64 * LL], hB[64 * LL];
    hA[t] = g_h1[l * 64 * LL + t];
    __syncthreads();

    int jm = j - 1; if (jm < 0) jm = 1;
    int jp = j + 1; if (jp > 7) jp = 6;

    float acc = bc1[o];
    {
        const float* w = Wc1 + o * 64 * 3;
        #pragma unroll 16
        for (int i = 0; i < 64; i++) {
            const float* xr = &hA[i * LL];
            acc += w[3*i] * xr[jm] + w[3*i+1] * xr[j] + w[3*i+2] * xr[jp];
        }
    }
    hB[o * LL + j] = fmaxf(acc, 0.f);
    __syncthreads();

    acc = bc2[o];
    {
        const float* w = Wc2 + o * 64 * 3;
        #pragma unroll 16
        for (int i = 0; i < 64; i++) {
            const float* xr = &hB[i * LL];
            acc += w[3*i] * xr[jm] + w[3*i+1] * xr[j] + w[3*i+2] * xr[jp];
        }
    }
    hA[o * LL + j] = fmaxf(acc, 0.f);
    __syncthreads();

    __shared__ float lf[64];
    if (j == 0) {
        float m = -FLT_MAX;
        #pragma unroll
        for (int k = 0; k < LL; k++) m = fmaxf(m, hA[o * LL + k]);
        lf[o] = m;
        g_loop_feat[l * FEAT + o] = m;
    }
    __syncthreads();

    __shared__ float gg[32];
    if (t < 32) {
        float a = bl1[t];
        #pragma unroll 8
        for (int i = 0; i < 64; i++) a += lf[i] * Wl1[t * 64 + i];
        gg[t] = fmaxf(a, 0.f) * Wl2[t];
    }
    __syncthreads();
    if (t == 0) {
        float s = bl2[0];
        #pragma unroll
        for (int i = 0; i < 32; i++) s += gg[i];
        out[OFF_LC + l] = 1.f / (1.f + expf(-s));
    }
}

// ---------------------------------------------------------------------------
// Kernel 5: loop-edge incidence (input-only; launched first to hide latency)
// ---------------------------------------------------------------------------
__global__ void k_loopedges(const int* __restrict__ loops,
                            const int* __restrict__ edge_corner,
                            float* __restrict__ out) {
    int l = blockIdx.x, e = threadIdx.x;       // 256 threads = edges
    __shared__ int ci[LL];
    if (e < LL) ci[e] = loops[l * LL + e];
    __syncthreads();
    int a = edge_corner[2 * e], b = edge_corner[2 * e + 1];
    float r = 0.f;
    #pragma unroll
    for (int j = 0; j < LL; j++) {
        int cj = ci[j];
        int cp = ci[(j + LL - 1) & 7];
        int cn = ci[(j + 1) & 7];
        if (cj == a && (cp == b || cn == b)) r = 1.f;
    }
    out[OFF_LE + l * E + e] = r;
}

// ---------------------------------------------------------------------------
// Kernel 6: confidence-weighted loop-feature average per edge + final 1x1 conv
// ---------------------------------------------------------------------------
__global__ void k_final(const float* __restrict__ coord,
                        const float* __restrict__ Wagg,
                        float* __restrict__ out) {
    int e = blockIdx.x, t = threadIdx.x;       // 128 threads
    __shared__ float cat[C + FEAT];            // 192
    __shared__ float lconf[NL];
    if (t < NL) lconf[t] = out[OFF_LC + t];
    if (t < C)  cat[t]   = coord[e * C + t];
    __syncthreads();
    if (t < FEAT) {
        float num = 0.f, den = 0.f;
        #pragma unroll 8
        for (int l = 0; l < NL; l++) {
            float w = lconf[l] * out[OFF_LE + l * E + e];
            num += w * g_loop_feat[l * FEAT + t];
            den += w;
        }
        cat[C + t] = num / fmaxf(den, 1e-4f);
    }
    __syncthreads();
    float acc = 0.f;
    const float* w = Wagg + t * (C + FEAT);
    #pragma unroll 8
    for (int i = 0; i < C + FEAT; i++) acc += cat[i] * w[i];
    out[e * C + t] = fmaxf(acc, 0.f);
}

// ---------------------------------------------------------------------------
extern "C" void kernel_launch(void* const* d_in, const int* in_sizes, int n_in,
                              void* d_out, int out_size) {
    const float* image_x = (const float*)d_in[0];
    const float* coord_x = (const float*)d_in[1];
    const float* corners = (const float*)d_in[2];
    const int*   pairs   = (const int*)  d_in[3];
    const int*   e_crn   = (const int*)  d_in[4];
    const int*   loops   = (const int*)  d_in[5];
    const float* W_ep1 = (const float*)d_in[6];
    const float* b_ep1 = (const float*)d_in[7];
    const float* W_ep2 = (const float*)d_in[8];
    const float* b_ep2 = (const float*)d_in[9];
    const float* Wc0 = (const float*)d_in[10];
    const float* bc0 = (const float*)d_in[11];
    const float* Wc1 = (const float*)d_in[12];
    const float* bc1 = (const float*)d_in[13];
    const float* Wc2 = (const float*)d_in[14];
    const float* bc2 = (const float*)d_in[15];
    const float* Wl1 = (const float*)d_in[16];
    const float* bl1 = (const float*)d_in[17];
    const float* Wl2 = (const float*)d_in[18];
    const float* bl2 = (const float*)d_in[19];
    const float* Wagg = (const float*)d_in[20];
    float* out = (float*)d_out;

    k_loopedges  <<<NL, 256>>>(loops, e_crn, out);       // input-only, run first
    k_maxpool    <<<E * C, 256>>>(image_x, coord_x);
    k_edge_corner<<<E + NC, 256>>>(W_ep1, b_ep1, W_ep2, b_ep2, pairs, out);
    {
        dim3 grid(8, NL);
        k_conv0 <<<grid, 256>>>(loops, corners, Wc0, bc0);
    }
    k_looprest   <<<NL, 512>>>(Wc1, bc1, Wc2, bc2, Wl1, bl1, Wl2, bl2, out);
    k_final      <<<E, 128>>>(coord_x, Wagg, out);
}

// round 5
// speedup vs baseline: 1.3568x; 1.0080x over previous
#include <cuda_runtime.h>
#include <float.h>
#include <math.h>

// Problem constants
#define E    256
#define C    128
#define HW   3136          // 56*56
#define NC   200
#define NP   512
#define NL   64
#define LL   8
#define ED   256           // EDGE_DIM = 2C
#define LIN  258           // LOOP_IN
#define FEAT 64
#define ZW   192           // 64 outputs * 3 taps
#define ZPAD 196           // padded row stride for conflict-free shared access

// Output layout (flattened concat of reference return tuple)
#define OFF_OUT 0
#define OFF_EC  (E*C)            // 32768
#define OFF_LC  (OFF_EC + E)     // 33024
#define OFF_LE  (OFF_LC + NL)    // 33088

// Device scratch (no allocation allowed)
__device__ float g_edge_x[E*ED];
__device__ float g_z[NC*ZW];         // per-corner conv0 partials z[c][o*3+k]
__device__ float g_loop_feat[NL*FEAT];
__device__ float g_Wt[LIN*ZW];       // transposed conv0 weights Wt[i][o*3+k]

// ---------------------------------------------------------------------------
// Kernel A (fused, input-only): blocks [0,NL) = loop-edge incidence;
// blocks [NL, NL+97) = conv0 weight transpose Wc0[o][i][k] -> Wt[i][o*3+k].
// ---------------------------------------------------------------------------
__global__ void k_prep(const int* __restrict__ loops,
                       const int* __restrict__ edge_corner,
                       const float* __restrict__ Wc0,
                       float* __restrict__ out) {
    int t = threadIdx.x;
    if (blockIdx.x < NL) {
        int l = blockIdx.x, e = t;             // 256 threads = edges
        __shared__ int ci[LL];
        if (e < LL) ci[e] = loops[l * LL + e];
        __syncthreads();
        int a = edge_corner[2 * e], b = edge_corner[2 * e + 1];
        float r = 0.f;
        #pragma unroll
        for (int j = 0; j < LL; j++) {
            int cj = ci[j];
            int cp = ci[(j + LL - 1) & 7];
            int cn = ci[(j + 1) & 7];
            if (cj == a && (cp == b || cn == b)) r = 1.f;
        }
        out[OFF_LE + l * E + e] = r;
    } else {
        int base = (blockIdx.x - NL) * 512;
        #pragma unroll
        for (int k = 0; k < 2; k++) {
            int d = base + t + k * 256;        // dest index i*ZW + ok
            if (d < LIN * ZW) {
                int i = d / ZW, ok = d - i * ZW;
                int o = ok / 3, kk = ok - o * 3;
                g_Wt[d] = Wc0[(o * LIN + i) * 3 + kk];
            }
        }
    }
}

// ---------------------------------------------------------------------------
// Kernel 1: per-(edge,channel) global max pool over 56x56 (411 MB HBM read)
// ---------------------------------------------------------------------------
__global__ void k_maxpool(const float* __restrict__ img,
                          const float* __restrict__ coord) {
    int ec = blockIdx.x;                       // e*C + c
    const float4* p = (const float4*)img + (size_t)ec * (HW / 4);
    float m = -FLT_MAX;
    #pragma unroll 4
    for (int i = threadIdx.x; i < HW / 4; i += blockDim.x) {
        float4 v = p[i];
        m = fmaxf(m, fmaxf(fmaxf(v.x, v.y), fmaxf(v.z, v.w)));
    }
    #pragma unroll
    for (int off = 16; off > 0; off >>= 1)
        m = fmaxf(m, __shfl_xor_sync(0xFFFFFFFFu, m, off));
    __shared__ float s[8];
    int lane = threadIdx.x & 31, wid = threadIdx.x >> 5;
    if (lane == 0) s[wid] = m;
    __syncthreads();
    if (threadIdx.x == 0) {
        float mm = s[0];
        #pragma unroll
        for (int w = 1; w < 8; w++) mm = fmaxf(mm, s[w]);
        int e = ec >> 7, c = ec & 127;
        g_edge_x[e * ED + c]     = mm;
        g_edge_x[e * ED + C + c] = coord[ec];
    }
}

// ---------------------------------------------------------------------------
// Kernel 2 (fused): blocks [0,E) = edge-conf MLP;
// blocks [E, E+NC) = corner scatter-mean + per-corner conv0 GEMM row.
// 256 threads everywhere.
// ---------------------------------------------------------------------------
__global__ void k_edge_corner(const float* __restrict__ W1, const float* __restrict__ b1,
                              const float* __restrict__ W2, const float* __restrict__ b2,
                              const int* __restrict__ pairs,
                              const float* __restrict__ corners,
                              float* __restrict__ out) {
    int t = threadIdx.x;
    if (blockIdx.x < E) {
        // ---- edge confidence for edge e ----
        int e = blockIdx.x;
        __shared__ float sx[ED];
        __shared__ float sr[64];
        for (int i = t; i < ED; i += 256) sx[i] = g_edge_x[e * ED + i];
        __syncthreads();
        int ks = t & 3, o = t >> 2;
        float acc = 0.f;
        #pragma unroll 16
        for (int i = ks; i < ED; i += 4) acc += sx[i] * W1[o * ED + i];
        acc += __shfl_down_sync(0xFFFFFFFFu, acc, 1);
        acc += __shfl_down_sync(0xFFFFFFFFu, acc, 2);
        if (ks == 0) sr[o] = fmaxf(acc + b1[o], 0.f) * W2[o];
        __syncthreads();
        if (t < 32) {
            float v = sr[t] + sr[t + 32];
            #pragma unroll
            for (int off = 16; off > 0; off >>= 1)
                v += __shfl_xor_sync(0xFFFFFFFFu, v, off);
            if (t == 0) out[OFF_EC + e] = 1.f / (1.f + expf(-(v + b2[0])));
        }
    } else {
        // ---- corner scatter-mean + GEMM row for corner c ----
        int c = blockIdx.x - E;
        __shared__ unsigned mask[NP / 32];
        __shared__ int sedge[NP];
        __shared__ float sfeat[LIN];
        if (t < NP / 32) mask[t] = 0u;
        __syncthreads();
        #pragma unroll
        for (int k = 0; k < 2; k++) {
            int p = t + k * 256;
            int2 pr = ((const int2*)pairs)[p];
            sedge[p] = pr.y;
            if (pr.x == c) atomicOr(&mask[p >> 5], 1u << (p & 31));
        }
        __syncthreads();
        // per-channel mean in increasing pair order (deterministic)
        float sum = 0.f, cnt = 0.f;
        #pragma unroll
        for (int w = 0; w < NP / 32; w++) {
            unsigned m = mask[w];
            while (m) {
                int b = __ffs(m) - 1;
                m &= m - 1;
                sum += g_edge_x[sedge[w * 32 + b] * ED + t];
                cnt += 1.f;
            }
        }
        sfeat[t] = sum / fmaxf(cnt, 1.f);
        if (t < 2) sfeat[ED + t] = corners[c * 2 + t];
        __syncthreads();
        // GEMM row: z[c][ok] = sum_i sfeat[i] * Wt[i][ok], ok in [0,192)
        if (t < ZW) {
            float a0 = 0.f, a1 = 0.f;
            int i = 0;
            #pragma unroll 4
            for (; i + 1 < LIN; i += 2) {
                a0 += sfeat[i]     * g_Wt[i * ZW + t];
                a1 += sfeat[i + 1] * g_Wt[(i + 1) * ZW + t];
            }
            for (; i < LIN; i++) a0 += sfeat[i] * g_Wt[i * ZW + t];
            g_z[c * ZW + t] = a0 + a1;
        }
    }
}

// ---------------------------------------------------------------------------
// Kernel 3: full LoopEncoder from z: assemble conv0 output via 3 z-taps,
// then conv1 + conv2 + max over L + loop-conf MLP.
// grid = NL, 512 threads = (o:64, j:8).
// ---------------------------------------------------------------------------
__global__ void k_looprest(const int* __restrict__ loops,
                           const float* __restrict__ bc0,
                           const float* __restrict__ Wc1, const float* __restrict__ bc1,
                           const float* __restrict__ Wc2, const float* __restrict__ bc2,
                           const float* __restrict__ Wl1, const float* __restrict__ bl1,
                           const float* __restrict__ Wl2, const float* __restrict__ bl2,
                           float* __restrict__ out) {
    int l = blockIdx.x, t = threadIdx.x;
    int o = t >> 3, j = t & 7;
    __shared__ int   ci[LL];
    __shared__ float zz[LL * ZPAD];            // z rows for the loop's 8 corners
    __shared__ float hA[64 * LL], hB[64 * LL];
    if (t < LL) ci[t] = loops[l * LL + t];
    __syncthreads();
    for (int idx = t; idx < LL * ZW; idx += 512) {
        int jj = idx / ZW, ok = idx - jj * ZW;
        zz[jj * ZPAD + ok] = g_z[ci[jj] * ZW + ok];
    }
    __syncthreads();

    int jm = j - 1; if (jm < 0) jm = 1;        // ReflectionPad1d(1)
    int jp = j + 1; if (jp > 7) jp = 6;

    // conv0 assembly: 3 taps from z
    float acc = bc0[o]
              + zz[jm * ZPAD + o * 3 + 0]
              + zz[j  * ZPAD + o * 3 + 1]
              + zz[jp * ZPAD + o * 3 + 2];
    hA[o * LL + j] = fmaxf(acc, 0.f);
    __syncthreads();

    // conv1: 64 -> 64
    acc = bc1[o];
    {
        const float* w = Wc1 + o * 64 * 3;
        #pragma unroll 16
        for (int i = 0; i < 64; i++) {
            const float* xr = &hA[i * LL];
            acc += w[3*i] * xr[jm] + w[3*i+1] * xr[j] + w[3*i+2] * xr[jp];
        }
    }
    hB[o * LL + j] = fmaxf(acc, 0.f);
    __syncthreads();

    // conv2: 64 -> 64
    acc = bc2[o];
    {
        const float* w = Wc2 + o * 64 * 3;
        #pragma unroll 16
        for (int i = 0; i < 64; i++) {
            const float* xr = &hB[i * LL];
            acc += w[3*i] * xr[jm] + w[3*i+1] * xr[j] + w[3*i+2] * xr[jp];
        }
    }
    hA[o * LL + j] = fmaxf(acc, 0.f);
    __syncthreads();

    __shared__ float lf[64];
    if (j == 0) {
        float m = -FLT_MAX;
        #pragma unroll
        for (int k = 0; k < LL; k++) m = fmaxf(m, hA[o * LL + k]);
        lf[o] = m;
        g_loop_feat[l * FEAT + o] = m;
    }
    __syncthreads();

    __shared__ float gg[32];
    if (t < 32) {
        float a = bl1[t];
        #pragma unroll 8
        for (int i = 0; i < 64; i++) a += lf[i] * Wl1[t * 64 + i];
        gg[t] = fmaxf(a, 0.f) * Wl2[t];
    }
    __syncthreads();
    if (t == 0) {
        float s = bl2[0];
        #pragma unroll
        for (int i = 0; i < 32; i++) s += gg[i];
        out[OFF_LC + l] = 1.f / (1.f + expf(-s));
    }
}

// ---------------------------------------------------------------------------
// Kernel 4: confidence-weighted loop-feature average per edge + final 1x1 conv
// ---------------------------------------------------------------------------
__global__ void k_final(const float* __restrict__ coord,
                        const float* __restrict__ Wagg,
                        float* __restrict__ out) {
    int e = blockIdx.x, t = threadIdx.x;       // 128 threads
    __shared__ float cat[C + FEAT];
    __shared__ float lconf[NL];
    if (t < NL) lconf[t] = out[OFF_LC + t];
    if (t < C)  cat[t]   = coord[e * C + t];
    __syncthreads();
    if (t < FEAT) {
        float num = 0.f, den = 0.f;
        #pragma unroll 8
        for (int l = 0; l < NL; l++) {
            float w = lconf[l] * out[OFF_LE + l * E + e];
            num += w * g_loop_feat[l * FEAT + t];
            den += w;
        }
        cat[C + t] = num / fmaxf(den, 1e-4f);
    }
    __syncthreads();
    float acc = 0.f;
    const float* w = Wagg + t * (C + FEAT);
    #pragma unroll 8
    for (int i = 0; i < C + FEAT; i++) acc += cat[i] * w[i];
    out[e * C + t] = fmaxf(acc, 0.f);
}

// ---------------------------------------------------------------------------
extern "C" void kernel_launch(void* const* d_in, const int* in_sizes, int n_in,
                              void* d_out, int out_size) {
    const float* image_x = (const float*)d_in[0];
    const float* coord_x = (const float*)d_in[1];
    const float* corners = (const float*)d_in[2];
    const int*   pairs   = (const int*)  d_in[3];
    const int*   e_crn   = (const int*)  d_in[4];
    const int*   loops   = (const int*)  d_in[5];
    const float* W_ep1 = (const float*)d_in[6];
    const float* b_ep1 = (const float*)d_in[7];
    const float* W_ep2 = (const float*)d_in[8];
    const float* b_ep2 = (const float*)d_in[9];
    const float* Wc0 = (const float*)d_in[10];
    const float* bc0 = (const float*)d_in[11];
    const float* Wc1 = (const float*)d_in[12];
    const float* bc1 = (const float*)d_in[13];
    const float* Wc2 = (const float*)d_in[14];
    const float* bc2 = (const float*)d_in[15];
    const float* Wl1 = (const float*)d_in[16];
    const float* bl1 = (const float*)d_in[17];
    const float* Wl2 = (const float*)d_in[18];
    const float* bl2 = (const float*)d_in[19];
    const float* Wagg = (const float*)d_in[20];
    float* out = (float*)d_out;

    k_prep       <<<NL + 97, 256>>>(loops, e_crn, Wc0, out);   // input-only
    k_maxpool    <<<E * C, 256>>>(image_x, coord_x);
    k_edge_corner<<<E + NC, 256>>>(W_ep1, b_ep1, W_ep2, b_ep2, pairs, corners, out);
    k_looprest   <<<NL, 512>>>(loops, bc0, Wc1, bc1, Wc2, bc2,
                               Wl1, bl1, Wl2, bl2, out);
    k_final      <<<E, 128>>>(coord_x, Wagg, out);
}

// round 6
// speedup vs baseline: 1.5720x; 1.1586x over previous
#include <cuda_runtime.h>
#include <float.h>
#include <math.h>

// Problem constants
#define E    256
#define C    128
#define HW   3136          // 56*56
#define NC   200
#define NP   512
#define NL   64
#define LL   8
#define ED   256           // EDGE_DIM = 2C
#define LIN  258           // LOOP_IN
#define FEAT 64
#define ZW   192           // 64 outputs * 3 taps
#define ZPAD 196           // padded row stride

// Output layout (flattened concat of reference return tuple)
#define OFF_OUT 0
#define OFF_EC  (E*C)            // 32768
#define OFF_LC  (OFF_EC + E)     // 33024
#define OFF_LE  (OFF_LC + NL)    // 33088

// Device scratch (no allocation allowed)
__device__ float g_edge_x[E*ED];
__device__ float g_z[NC*ZW];         // per-corner conv0 partials z[c][o*3+k]
__device__ float g_h2[NL*64*LL];     // conv1 output
__device__ float g_loop_feat[NL*FEAT];
__device__ float g_Wt[LIN*ZW];       // transposed conv0 weights Wt[i][o*3+k]

// ---------------------------------------------------------------------------
// Kernel 1 (fused): blocks [0, E*C) = per-(edge,channel) max pool (411 MB HBM,
// the dominant cost); blocks [E*C, E*C+NL) = loop-edge incidence; blocks
// [E*C+NL, ...) = conv0 weight transpose. The small blocks ride free under
// the DRAM-bound pool.
// ---------------------------------------------------------------------------
__global__ void k_pool_prep(const float* __restrict__ img,
                            const float* __restrict__ coord,
                            const int* __restrict__ loops,
                            const int* __restrict__ edge_corner,
                            const float* __restrict__ Wc0,
                            float* __restrict__ out) {
    int t = threadIdx.x;
    if (blockIdx.x < E * C) {
        int ec = blockIdx.x;                   // e*C + c
        const float4* p = (const float4*)img + (size_t)ec * (HW / 4);
        float m = -FLT_MAX;
        #pragma unroll 4
        for (int i = t; i < HW / 4; i += 256) {
            float4 v = p[i];
            m = fmaxf(m, fmaxf(fmaxf(v.x, v.y), fmaxf(v.z, v.w)));
        }
        #pragma unroll
        for (int off = 16; off > 0; off >>= 1)
            m = fmaxf(m, __shfl_xor_sync(0xFFFFFFFFu, m, off));
        __shared__ float s[8];
        int lane = t & 31, wid = t >> 5;
        if (lane == 0) s[wid] = m;
        __syncthreads();
        if (t == 0) {
            float mm = s[0];
            #pragma unroll
            for (int w = 1; w < 8; w++) mm = fmaxf(mm, s[w]);
            int e = ec >> 7, c = ec & 127;
            g_edge_x[e * ED + c]     = mm;
            g_edge_x[e * ED + C + c] = coord[ec];
        }
    } else if (blockIdx.x < E * C + NL) {
        // loop-edge incidence for loop l
        int l = blockIdx.x - E * C, e = t;     // 256 threads = edges
        __shared__ int ci[LL];
        if (e < LL) ci[e] = loops[l * LL + e];
        __syncthreads();
        int a = edge_corner[2 * e], b = edge_corner[2 * e + 1];
        float r = 0.f;
        #pragma unroll
        for (int j = 0; j < LL; j++) {
            int cj = ci[j];
            int cp = ci[(j + LL - 1) & 7];
            int cn = ci[(j + 1) & 7];
            if (cj == a && (cp == b || cn == b)) r = 1.f;
        }
        out[OFF_LE + l * E + e] = r;
    } else {
        // conv0 weight transpose Wc0[o][i][k] -> Wt[i][o*3+k]
        int base = (blockIdx.x - E * C - NL) * 512;
        #pragma unroll
        for (int k = 0; k < 2; k++) {
            int d = base + t + k * 256;
            if (d < LIN * ZW) {
                int i = d / ZW, ok = d - i * ZW;
                int o = ok / 3, kk = ok - o * 3;
                g_Wt[d] = Wc0[(o * LIN + i) * 3 + kk];
            }
        }
    }
}

// ---------------------------------------------------------------------------
// Kernel 2 (fused): blocks [0,E) = edge-conf MLP;
// blocks [E, E+NC) = corner scatter-mean + per-corner conv0 GEMM row.
// ---------------------------------------------------------------------------
__global__ void k_edge_corner(const float* __restrict__ W1, const float* __restrict__ b1,
                              const float* __restrict__ W2, const float* __restrict__ b2,
                              const int* __restrict__ pairs,
                              const float* __restrict__ corners,
                              float* __restrict__ out) {
    int t = threadIdx.x;
    if (blockIdx.x < E) {
        int e = blockIdx.x;
        __shared__ float sx[ED];
        __shared__ float sr[64];
        for (int i = t; i < ED; i += 256) sx[i] = g_edge_x[e * ED + i];
        __syncthreads();
        int ks = t & 3, o = t >> 2;
        float acc = 0.f;
        #pragma unroll 16
        for (int i = ks; i < ED; i += 4) acc += sx[i] * W1[o * ED + i];
        acc += __shfl_down_sync(0xFFFFFFFFu, acc, 1);
        acc += __shfl_down_sync(0xFFFFFFFFu, acc, 2);
        if (ks == 0) sr[o] = fmaxf(acc + b1[o], 0.f) * W2[o];
        __syncthreads();
        if (t < 32) {
            float v = sr[t] + sr[t + 32];
            #pragma unroll
            for (int off = 16; off > 0; off >>= 1)
                v += __shfl_xor_sync(0xFFFFFFFFu, v, off);
            if (t == 0) out[OFF_EC + e] = 1.f / (1.f + expf(-(v + b2[0])));
        }
    } else {
        int c = blockIdx.x - E;
        __shared__ unsigned mask[NP / 32];
        __shared__ int sedge[NP];
        __shared__ float sfeat[LIN];
        if (t < NP / 32) mask[t] = 0u;
        __syncthreads();
        #pragma unroll
        for (int k = 0; k < 2; k++) {
            int p = t + k * 256;
            int2 pr = ((const int2*)pairs)[p];
            sedge[p] = pr.y;
            if (pr.x == c) atomicOr(&mask[p >> 5], 1u << (p & 31));
        }
        __syncthreads();
        float sum = 0.f, cnt = 0.f;
        #pragma unroll
        for (int w = 0; w < NP / 32; w++) {
            unsigned m = mask[w];
            while (m) {
                int b = __ffs(m) - 1;
                m &= m - 1;
                sum += g_edge_x[sedge[w * 32 + b] * ED + t];
                cnt += 1.f;
            }
        }
        sfeat[t] = sum / fmaxf(cnt, 1.f);
        if (t < 2) sfeat[ED + t] = corners[c * 2 + t];
        __syncthreads();
        if (t < ZW) {
            float a0 = 0.f, a1 = 0.f;
            int i = 0;
            #pragma unroll 4
            for (; i + 1 < LIN; i += 2) {
                a0 += sfeat[i]     * g_Wt[i * ZW + t];
                a1 += sfeat[i + 1] * g_Wt[(i + 1) * ZW + t];
            }
            for (; i < LIN; i++) a0 += sfeat[i] * g_Wt[i * ZW + t];
            g_z[c * ZW + t] = a0 + a1;
        }
    }
}

// ---------------------------------------------------------------------------
// Kernel 3: conv0 assembly + conv1 (wide). grid = (4 o-groups, NL loops),
// 512 threads = (ks:4, j:8, o_local:16). Each thread: 16 iters + shfl reduce.
// ---------------------------------------------------------------------------
__global__ void k_conv1(const int* __restrict__ loops,
                        const float* __restrict__ bc0,
                        const float* __restrict__ Wc1, const float* __restrict__ bc1) {
    int l = blockIdx.y, bo = blockIdx.x, t = threadIdx.x;
    __shared__ int   ci[LL];
    __shared__ float zz[LL * ZPAD];
    __shared__ float hA[64 * LL];
    if (t < LL) ci[t] = loops[l * LL + t];
    __syncthreads();
    for (int idx = t; idx < LL * ZW; idx += 512) {
        int jj = idx / ZW, ok = idx - jj * ZW;
        zz[jj * ZPAD + ok] = g_z[ci[jj] * ZW + ok];
    }
    __syncthreads();
    {   // conv0 assembly: one hA value per thread
        int o = t >> 3, j = t & 7;
        int jm = j - 1; if (jm < 0) jm = 1;
        int jp = j + 1; if (jp > 7) jp = 6;
        float a = bc0[o] + zz[jm * ZPAD + o * 3]
                         + zz[j  * ZPAD + o * 3 + 1]
                         + zz[jp * ZPAD + o * 3 + 2];
        hA[o * LL + j] = fmaxf(a, 0.f);
    }
    __syncthreads();

    int ks = t & 3, j = (t >> 2) & 7, ol = t >> 5;
    int o = bo * 16 + ol;
    int jm = j - 1; if (jm < 0) jm = 1;
    int jp = j + 1; if (jp > 7) jp = 6;
    float acc = 0.f;
    #pragma unroll
    for (int i = ks; i < 64; i += 4) {
        const float* w = Wc1 + (o * 64 + i) * 3;
        acc += w[0] * hA[i * 8 + jm] + w[1] * hA[i * 8 + j] + w[2] * hA[i * 8 + jp];
    }
    acc += __shfl_down_sync(0xFFFFFFFFu, acc, 1);
    acc += __shfl_down_sync(0xFFFFFFFFu, acc, 2);
    if (ks == 0)
        g_h2[(l * 64 + o) * LL + j] = fmaxf(acc + bc1[o], 0.f);
}

// ---------------------------------------------------------------------------
// Kernel 4: conv2 + max over L + loop-conf MLP.
// grid = NL, 1024 threads = (ks:2, j:8, o:64): 32 iters/thread + shfl reduce.
// ---------------------------------------------------------------------------
__global__ void __launch_bounds__(1024, 1)
k_conv2fin(const float* __restrict__ Wc2, const float* __restrict__ bc2,
           const float* __restrict__ Wl1, const float* __restrict__ bl1,
           const float* __restrict__ Wl2, const float* __restrict__ bl2,
           float* __restrict__ out) {
    int l = blockIdx.x, t = threadIdx.x;
    __shared__ float hB[64 * LL];
    __shared__ float hC[64 * LL];
    if (t < 512) hB[t] = g_h2[l * 512 + t];
    __syncthreads();

    int ks = t & 1, j = (t >> 1) & 7, o = t >> 4;
    int jm = j - 1; if (jm < 0) jm = 1;
    int jp = j + 1; if (jp > 7) jp = 6;
    float acc = 0.f;
    #pragma unroll
    for (int i = ks; i < 64; i += 2) {
        const float* w = Wc2 + (o * 64 + i) * 3;
        acc += w[0] * hB[i * 8 + jm] + w[1] * hB[i * 8 + j] + w[2] * hB[i * 8 + jp];
    }
    acc += __shfl_down_sync(0xFFFFFFFFu, acc, 1);
    if (ks == 0) hC[o * LL + j] = fmaxf(acc + bc2[o], 0.f);
    __syncthreads();

    __shared__ float lf[64];
    if (t < 64) {
        float m = -FLT_MAX;
        #pragma unroll
        for (int k = 0; k < LL; k++) m = fmaxf(m, hC[t * LL + k]);
        lf[t] = m;
        g_loop_feat[l * FEAT + t] = m;
    }
    __syncthreads();

    __shared__ float gg[32];
    if (t < 32) {
        float a = bl1[t];
        #pragma unroll 8
        for (int i = 0; i < 64; i++) a += lf[i] * Wl1[t * 64 + i];
        gg[t] = fmaxf(a, 0.f) * Wl2[t];
    }
    __syncthreads();
    if (t == 0) {
        float s = bl2[0];
        #pragma unroll
        for (int i = 0; i < 32; i++) s += gg[i];
        out[OFF_LC + l] = 1.f / (1.f + expf(-s));
    }
}

// ---------------------------------------------------------------------------
// Kernel 5: confidence-weighted loop-feature average per edge + final 1x1 conv
// ---------------------------------------------------------------------------
__global__ void k_final(const float* __restrict__ coord,
                        const float* __restrict__ Wagg,
                        float* __restrict__ out) {
    int e = blockIdx.x, t = threadIdx.x;       // 128 threads
    __shared__ float cat[C + FEAT];
    __shared__ float lconf[NL];
    if (t < NL) lconf[t] = out[OFF_LC + t];
    if (t < C)  cat[t]   = coord[e * C + t];
    __syncthreads();
    if (t < FEAT) {
        float num = 0.f, den = 0.f;
        #pragma unroll 8
        for (int l = 0; l < NL; l++) {
            float w = lconf[l] * out[OFF_LE + l * E + e];
            num += w * g_loop_feat[l * FEAT + t];
            den += w;
        }
        cat[C + t] = num / fmaxf(den, 1e-4f);
    }
    __syncthreads();
    float acc = 0.f;
    const float* w = Wagg + t * (C + FEAT);
    #pragma unroll 8
    for (int i = 0; i < C + FEAT; i++) acc += cat[i] * w[i];
    out[e * C + t] = fmaxf(acc, 0.f);
}

// ---------------------------------------------------------------------------
extern "C" void kernel_launch(void* const* d_in, const int* in_sizes, int n_in,
                              void* d_out, int out_size) {
    const float* image_x = (const float*)d_in[0];
    const float* coord_x = (const float*)d_in[1];
    const float* corners = (const float*)d_in[2];
    const int*   pairs   = (const int*)  d_in[3];
    const int*   e_crn   = (const int*)  d_in[4];
    const int*   loops   = (const int*)  d_in[5];
    const float* W_ep1 = (const float*)d_in[6];
    const float* b_ep1 = (const float*)d_in[7];
    const float* W_ep2 = (const float*)d_in[8];
    const float* b_ep2 = (const float*)d_in[9];
    const float* Wc0 = (const float*)d_in[10];
    const float* bc0 = (const float*)d_in[11];
    const float* Wc1 = (const float*)d_in[12];
    const float* bc1 = (const float*)d_in[13];
    const float* Wc2 = (const float*)d_in[14];
    const float* bc2 = (const float*)d_in[15];
    const float* Wl1 = (const float*)d_in[16];
    const float* bl1 = (const float*)d_in[17];
    const float* Wl2 = (const float*)d_in[18];
    const float* bl2 = (const float*)d_in[19];
    const float* Wagg = (const float*)d_in[20];
    float* out = (float*)d_out;

    k_pool_prep  <<<E * C + NL + 97, 256>>>(image_x, coord_x, loops, e_crn, Wc0, out);
    k_edge_corner<<<E + NC, 256>>>(W_ep1, b_ep1, W_ep2, b_ep2, pairs, corners, out);
    {
        dim3 grid(4, NL);
        k_conv1 <<<grid, 512>>>(loops, bc0, Wc1, bc1);
    }
    k_conv2fin   <<<NL, 1024>>>(Wc2, bc2, Wl1, bl1, Wl2, bl2, out);
    k_final      <<<E, 128>>>(coord_x, Wagg, out);
}

// round 10
// speedup vs baseline: 1.5942x; 1.0142x over previous
#include <cuda_runtime.h>
#include <float.h>
#include <math.h>

// Problem constants
#define E    256
#define C    128
#define HW   3136          // 56*56
#define NC   200
#define NP   512
#define NL   64
#define LL   8
#define ED   256           // EDGE_DIM = 2C
#define LIN  258           // LOOP_IN
#define FEAT 64
#define ZW   192           // 64 outputs * 3 taps
#define ZPAD 196           // padded row stride

// Output layout (flattened concat of reference return tuple)
#define OFF_OUT 0
#define OFF_EC  (E*C)            // 32768
#define OFF_LC  (OFF_EC + E)     // 33024
#define OFF_LE  (OFF_LC + NL)    // 33088

// Device scratch (no allocation allowed)
__device__ float g_edge_x[E*ED];
__device__ float g_z[NC*ZW];         // per-corner conv0 partials z[c][o*3+k]
__device__ float g_h2[NL*64*LL];     // conv1 output
__device__ float g_loop_feat[NL*FEAT];
__device__ float g_Wt[LIN*ZW];       // transposed conv0 weights Wt[i][o*3+k]

// ---------------------------------------------------------------------------
// Kernel 1 (fused): blocks [0, E*C) = per-(edge,channel) max pool (411 MB HBM,
// dominant cost); blocks [E*C, E*C+NL) = loop-edge incidence; rest = conv0
// weight transpose. Small blocks ride free under the DRAM-bound pool.
// ---------------------------------------------------------------------------
__global__ void k_pool_prep(const float* __restrict__ img,
                            const float* __restrict__ coord,
                            const int* __restrict__ loops,
                            const int* __restrict__ edge_corner,
                            const float* __restrict__ Wc0,
                            float* __restrict__ out) {
    int t = threadIdx.x;
    if (blockIdx.x < E * C) {
        int ec = blockIdx.x;                   // e*C + c
        const float4* p = (const float4*)img + (size_t)ec * (HW / 4);
        float m = -FLT_MAX;
        #pragma unroll 4
        for (int i = t; i < HW / 4; i += 256) {
            float4 v = p[i];
            m = fmaxf(m, fmaxf(fmaxf(v.x, v.y), fmaxf(v.z, v.w)));
        }
        #pragma unroll
        for (int off = 16; off > 0; off >>= 1)
            m = fmaxf(m, __shfl_xor_sync(0xFFFFFFFFu, m, off));
        __shared__ float s[8];
        int lane = t & 31, wid = t >> 5;
        if (lane == 0) s[wid] = m;
        __syncthreads();
        if (t == 0) {
            float mm = s[0];
            #pragma unroll
            for (int w = 1; w < 8; w++) mm = fmaxf(mm, s[w]);
            int e = ec >> 7, c = ec & 127;
            g_edge_x[e * ED + c]     = mm;
            g_edge_x[e * ED + C + c] = coord[ec];
        }
    } else if (blockIdx.x < E * C + NL) {
        int l = blockIdx.x - E * C, e = t;     // 256 threads = edges
        __shared__ int ci[LL];
        if (e < LL) ci[e] = loops[l * LL + e];
        __syncthreads();
        int a = edge_corner[2 * e], b = edge_corner[2 * e + 1];
        float r = 0.f;
        #pragma unroll
        for (int j = 0; j < LL; j++) {
            int cj = ci[j];
            int cp = ci[(j + LL - 1) & 7];
            int cn = ci[(j + 1) & 7];
            if (cj == a && (cp == b || cn == b)) r = 1.f;
        }
        out[OFF_LE + l * E + e] = r;
    } else {
        int base = (blockIdx.x - E * C - NL) * 512;
        #pragma unroll
        for (int k = 0; k < 2; k++) {
            int d = base + t + k * 256;
            if (d < LIN * ZW) {
                int i = d / ZW, ok = d - i * ZW;
                int o = ok / 3, kk = ok - o * 3;
                g_Wt[d] = Wc0[(o * LIN + i) * 3 + kk];
            }
        }
    }
}

// ---------------------------------------------------------------------------
// Kernel 2 (fused): blocks [0,E) = edge-conf MLP;
// blocks [E, E+NC) = corner scatter-mean + per-corner conv0 GEMM row.
// ---------------------------------------------------------------------------
__global__ void k_edge_corner(const float* __restrict__ W1, const float* __restrict__ b1,
                              const float* __restrict__ W2, const float* __restrict__ b2,
                              const int* __restrict__ pairs,
                              const float* __restrict__ corners,
                              float* __restrict__ out) {
    int t = threadIdx.x;
    if (blockIdx.x < E) {
        int e = blockIdx.x;
        __shared__ float sx[ED];
        __shared__ float sr[64];
        for (int i = t; i < ED; i += 256) sx[i] = g_edge_x[e * ED + i];
        __syncthreads();
        int ks = t & 3, o = t >> 2;
        float acc = 0.f;
        #pragma unroll 16
        for (int i = ks; i < ED; i += 4) acc += sx[i] * W1[o * ED + i];
        acc += __shfl_down_sync(0xFFFFFFFFu, acc, 1);
        acc += __shfl_down_sync(0xFFFFFFFFu, acc, 2);
        if (ks == 0) sr[o] = fmaxf(acc + b1[o], 0.f) * W2[o];
        __syncthreads();
        if (t < 32) {
            float v = sr[t] + sr[t + 32];
            #pragma unroll
            for (int off = 16; off > 0; off >>= 1)
                v += __shfl_xor_sync(0xFFFFFFFFu, v, off);
            if (t == 0) out[OFF_EC + e] = 1.f / (1.f + expf(-(v + b2[0])));
        }
    } else {
        int c = blockIdx.x - E;
        __shared__ unsigned mask[NP / 32];
        __shared__ int sedge[NP];
        __shared__ float sfeat[LIN];
        if (t < NP / 32) mask[t] = 0u;
        __syncthreads();
        #pragma unroll
        for (int k = 0; k < 2; k++) {
            int p = t + k * 256;
            int2 pr = ((const int2*)pairs)[p];
            sedge[p] = pr.y;
            if (pr.x == c) atomicOr(&mask[p >> 5], 1u << (p & 31));
        }
        __syncthreads();
        float sum = 0.f, cnt = 0.f;
        #pragma unroll
        for (int w = 0; w < NP / 32; w++) {
            unsigned m = mask[w];
            while (m) {
                int b = __ffs(m) - 1;
                m &= m - 1;
                sum += g_edge_x[sedge[w * 32 + b] * ED + t];
                cnt += 1.f;
            }
        }
        sfeat[t] = sum / fmaxf(cnt, 1.f);
        if (t < 2) sfeat[ED + t] = corners[c * 2 + t];
        __syncthreads();
        // GEMM row with 4 accumulators for MLP against L2 latency
        if (t < ZW) {
            float a0 = 0.f, a1 = 0.f, a2 = 0.f, a3 = 0.f;
            int i = 0;
            #pragma unroll 2
            for (; i + 3 < LIN; i += 4) {
                a0 += sfeat[i]     * g_Wt[(i    ) * ZW + t];
                a1 += sfeat[i + 1] * g_Wt[(i + 1) * ZW + t];
                a2 += sfeat[i + 2] * g_Wt[(i + 2) * ZW + t];
                a3 += sfeat[i + 3] * g_Wt[(i + 3) * ZW + t];
            }
            for (; i < LIN; i++) a0 += sfeat[i] * g_Wt[i * ZW + t];
            g_z[c * ZW + t] = (a0 + a1) + (a2 + a3);
        }
    }
}

// ---------------------------------------------------------------------------
// Kernel 3: conv0 assembly + conv1 (wide). grid = (4, NL), 512 threads =
// (ks:4, j:8, o_local:16). 16 iters/thread + shfl reduce.
// ---------------------------------------------------------------------------
__global__ void k_conv1(const int* __restrict__ loops,
                        const float* __restrict__ bc0,
                        const float* __restrict__ Wc1, const float* __restrict__ bc1) {
    int l = blockIdx.y, bo = blockIdx.x, t = threadIdx.x;
    __shared__ int   ci[LL];
    __shared__ float zz[LL * ZPAD];
    __shared__ float hA[64 * LL];
    if (t < LL) ci[t] = loops[l * LL + t];
    __syncthreads();
    for (int idx = t; idx < LL * ZW; idx += 512) {
        int jj = idx / ZW, ok = idx - jj * ZW;
        zz[jj * ZPAD + ok] = g_z[ci[jj] * ZW + ok];
    }
    __syncthreads();
    {   // conv0 assembly
        int o = t >> 3, j = t & 7;
        int jm = j - 1; if (jm < 0) jm = 1;
        int jp = j + 1; if (jp > 7) jp = 6;
        float a = bc0[o] + zz[jm * ZPAD + o * 3]
                         + zz[j  * ZPAD + o * 3 + 1]
                         + zz[jp * ZPAD + o * 3 + 2];
        hA[o * LL + j] = fmaxf(a, 0.f);
    }
    __syncthreads();

    int ks = t & 3, j = (t >> 2) & 7, ol = t >> 5;
    int o = bo * 16 + ol;
    int jm = j - 1; if (jm < 0) jm = 1;
    int jp = j + 1; if (jp > 7) jp = 6;
    float acc = 0.f;
    #pragma unroll
    for (int i = ks; i < 64; i += 4) {
        const float* w = Wc1 + (o * 64 + i) * 3;
        acc += w[0] * hA[i * 8 + jm] + w[1] * hA[i * 8 + j] + w[2] * hA[i * 8 + jp];
    }
    acc += __shfl_down_sync(0xFFFFFFFFu, acc, 1);
    acc += __shfl_down_sync(0xFFFFFFFFu, acc, 2);
    if (ks == 0)
        g_h2[(l * 64 + o) * LL + j] = fmaxf(acc + bc1[o], 0.f);
}

// ---------------------------------------------------------------------------
// Kernel 4: conv2 (wide) with max-over-L fused via warp shuffles.
// grid = (4, NL), 512 threads = (ks:4, j:8, o_local:16).
// ---------------------------------------------------------------------------
__global__ void k_conv2(const float* __restrict__ Wc2, const float* __restrict__ bc2) {
    int l = blockIdx.y, bo = blockIdx.x, t = threadIdx.x;
    __shared__ float hB[64 * LL];
    hB[t] = g_h2[l * 512 + t];
    __syncthreads();

    int ks = t & 3, j = (t >> 2) & 7, ol = t >> 5;
    int o = bo * 16 + ol;
    int jm = j - 1; if (jm < 0) jm = 1;
    int jp = j + 1; if (jp > 7) jp = 6;
    float acc = 0.f;
    #pragma unroll
    for (int i = ks; i < 64; i += 4) {
        const float* w = Wc2 + (o * 64 + i) * 3;
        acc += w[0] * hB[i * 8 + jm] + w[1] * hB[i * 8 + j] + w[2] * hB[i * 8 + jp];
    }
    acc += __shfl_down_sync(0xFFFFFFFFu, acc, 1);
    acc += __shfl_down_sync(0xFFFFFFFFu, acc, 2);
    // lanes with ks==0 hold h[o][j]; fold ReLU then max over the 8 j-lanes
    float v = (ks == 0) ? fmaxf(acc + bc2[o], 0.f) : -FLT_MAX;
    v = fmaxf(v, __shfl_xor_sync(0xFFFFFFFFu, v, 4));
    v = fmaxf(v, __shfl_xor_sync(0xFFFFFFFFu, v, 8));
    v = fmaxf(v, __shfl_xor_sync(0xFFFFFFFFu, v, 16));
    if ((t & 31) == 0) g_loop_feat[l * FEAT + o] = v;
}

// ---------------------------------------------------------------------------
// Kernel 5: loop-conf MLP (tiny). grid = NL, 32 threads, register-resident.
// ---------------------------------------------------------------------------
__global__ void k_loopmlp(const float* __restrict__ Wl1, const float* __restrict__ bl1,
                          const float* __restrict__ Wl2, const float* __restrict__ bl2,
                          float* __restrict__ out) {
    int l = blockIdx.x, t = threadIdx.x;       // 32 threads
    float f0 = g_loop_feat[l * FEAT + t];
    float f1 = g_loop_feat[l * FEAT + 32 + t];
    float a = bl1[t];
    #pragma unroll
    for (int i = 0; i < 32; i++) {
        a += __shfl_sync(0xFFFFFFFFu, f0, i) * Wl1[t * 64 + i];
        a += __shfl_sync(0xFFFFFFFFu, f1, i) * Wl1[t * 64 + 32 + i];
    }
    float v = fmaxf(a, 0.f) * Wl2[t];
    #pragma unroll
    for (int off = 16; off > 0; off >>= 1)
        v += __shfl_xor_sync(0xFFFFFFFFu, v, off);
    if (t == 0) out[OFF_LC + l] = 1.f / (1.f + expf(-(v + bl2[0])));
}

// ---------------------------------------------------------------------------
// Kernel 6: confidence-weighted loop-feature average per edge + final 1x1 conv
// ---------------------------------------------------------------------------
__global__ void k_final(const float* __restrict__ coord,
                        const float* __restrict__ Wagg,
                        float* __restrict__ out) {
    int e = blockIdx.x, t = threadIdx.x;       // 128 threads
    __shared__ float cat[C + FEAT];
    __shared__ float lconf[NL];
    if (t < NL) lconf[t] = out[OFF_LC + t];
    if (t < C)  cat[t]   = coord[e * C + t];
    __syncthreads();
    if (t < FEAT) {
        float num = 0.f, den = 0.f;
        #pragma unroll 8
        for (int l = 0; l < NL; l++) {
            float w = lconf[l] * out[OFF_LE + l * E + e];
            num += w * g_loop_feat[l * FEAT + t];
            den += w;
        }
        cat[C + t] = num / fmaxf(den, 1e-4f);
    }
    __syncthreads();
    float acc = 0.f;
    const float* w = Wagg + t * (C + FEAT);
    #pragma unroll 8
    for (int i = 0; i < C + FEAT; i++) acc += cat[i] * w[i];
    out[e * C + t] = fmaxf(acc, 0.f);
}

// ---------------------------------------------------------------------------
extern "C" void kernel_launch(void* const* d_in, const int* in_sizes, int n_in,
                              void* d_out, int out_size) {
    const float* image_x = (const float*)d_in[0];
    const float* coord_x = (const float*)d_in[1];
    const float* corners = (const float*)d_in[2];
    const int*   pairs   = (const int*)  d_in[3];
    const int*   e_crn   = (const int*)  d_in[4];
    const int*   loops   = (const int*)  d_in[5];
    const float* W_ep1 = (const float*)d_in[6];
    const float* b_ep1 = (const float*)d_in[7];
    const float* W_ep2 = (const float*)d_in[8];
    const float* b_ep2 = (const float*)d_in[9];
    const float* Wc0 = (const float*)d_in[10];
    const float* bc0 = (const float*)d_in[11];
    const float* Wc1 = (const float*)d_in[12];
    const float* bc1 = (const float*)d_in[13];
    const float* Wc2 = (const float*)d_in[14];
    const float* bc2 = (const float*)d_in[15];
    const float* Wl1 = (const float*)d_in[16];
    const float* bl1 = (const float*)d_in[17];
    const float* Wl2 = (const float*)d_in[18];
    const float* bl2 = (const float*)d_in[19];
    const float* Wagg = (const float*)d_in[20];
    float* out = (float*)d_out;

    k_pool_prep  <<<E * C + NL + 97, 256>>>(image_x, coord_x, loops, e_crn, Wc0, out);
    k_edge_corner<<<E + NC, 256>>>(W_ep1, b_ep1, W_ep2, b_ep2, pairs, corners, out);
    {
        dim3 grid(4, NL);
        k_conv1 <<<grid, 512>>>(loops, bc0, Wc1, bc1);
        k_conv2 <<<grid, 512>>>(Wc2, bc2);
    }
    k_loopmlp    <<<NL, 32>>>(Wl1, bl1, Wl2, bl2, out);
    k_final      <<<E, 128>>>(coord_x, Wagg, out);
}

// round 11
// speedup vs baseline: 1.8412x; 1.1549x over previous
#include <cuda_runtime.h>
#include <float.h>
#include <math.h>

// Problem constants
#define E    256
#define C    128
#define HW   3136          // 56*56
#define NC   200
#define NP   512
#define NL   64
#define LL   8
#define ED   256           // EDGE_DIM = 2C
#define LIN  258           // LOOP_IN
#define FEAT 64
#define ZW   192           // 64 outputs * 3 taps
#define ZPAD 196           // padded row stride
#define POOLB (E*C/8)      // 4096 pool blocks, 8 warps = 8 channels each

// Output layout (flattened concat of reference return tuple)
#define OFF_OUT 0
#define OFF_EC  (E*C)            // 32768
#define OFF_LC  (OFF_EC + E)     // 33024
#define OFF_LE  (OFF_LC + NL)    // 33088

// Device scratch (no allocation allowed)
__device__ float g_edge_x[E*ED];
__device__ float g_z[NC*ZW];         // per-corner conv0 partials z[c][o*3+k]
__device__ float g_h2[NL*64*LL];     // conv1 output
__device__ float g_loop_feat[NL*FEAT];
__device__ float g_Wt[LIN*ZW];       // transposed conv0 weights Wt[i][o*3+k]

// ---------------------------------------------------------------------------
// Kernel 1 (fused): blocks [0, POOLB) = warp-per-channel max pool (411 MB HBM
// read, the dominant cost; 24 independent float4 loads per lane, no smem, no
// block barrier); blocks [POOLB, POOLB+NL) = loop-edge incidence; rest =
// conv0 weight transpose. Small blocks ride free under the DRAM-bound pool.
// ---------------------------------------------------------------------------
__global__ void k_pool_prep(const float* __restrict__ img,
                            const float* __restrict__ coord,
                            const int* __restrict__ loops,
                            const int* __restrict__ edge_corner,
                            const float* __restrict__ Wc0,
                            float* __restrict__ out) {
    int t = threadIdx.x;
    if (blockIdx.x < POOLB) {
        int wid = t >> 5, lane = t & 31;
        int ec = blockIdx.x * 8 + wid;         // e*C + c, one channel per warp
        const float4* p = (const float4*)img + (size_t)ec * (HW / 4);
        float m = -FLT_MAX;
        // 784 float4 per channel, 32 lanes -> 24..25 independent loads/lane
        int i = lane;
        #pragma unroll 6
        for (; i < 768; i += 32) {
            float4 v = p[i];
            m = fmaxf(m, fmaxf(fmaxf(v.x, v.y), fmaxf(v.z, v.w)));
        }
        if (i < HW / 4) {                      // tail (784-768 = 16 lanes)
            float4 v = p[i];
            m = fmaxf(m, fmaxf(fmaxf(v.x, v.y), fmaxf(v.z, v.w)));
        }
        #pragma unroll
        for (int off = 16; off > 0; off >>= 1)
            m = fmaxf(m, __shfl_xor_sync(0xFFFFFFFFu, m, off));
        if (lane == 0) {
            int e = ec >> 7, c = ec & 127;
            g_edge_x[e * ED + c]     = m;
            g_edge_x[e * ED + C + c] = coord[ec];
        }
    } else if (blockIdx.x < POOLB + NL) {
        int l = blockIdx.x - POOLB, e = t;     // 256 threads = edges
        __shared__ int ci[LL];
        if (e < LL) ci[e] = loops[l * LL + e];
        __syncthreads();
        int a = edge_corner[2 * e], b = edge_corner[2 * e + 1];
        float r = 0.f;
        #pragma unroll
        for (int j = 0; j < LL; j++) {
            int cj = ci[j];
            int cp = ci[(j + LL - 1) & 7];
            int cn = ci[(j + 1) & 7];
            if (cj == a && (cp == b || cn == b)) r = 1.f;
        }
        out[OFF_LE + l * E + e] = r;
    } else {
        int base = (blockIdx.x - POOLB - NL) * 512;
        #pragma unroll
        for (int k = 0; k < 2; k++) {
            int d = base + t + k * 256;
            if (d < LIN * ZW) {
                int i = d / ZW, ok = d - i * ZW;
                int o = ok / 3, kk = ok - o * 3;
                g_Wt[d] = Wc0[(o * LIN + i) * 3 + kk];
            }
        }
    }
}

// ---------------------------------------------------------------------------
// Kernel 2 (fused): blocks [0,E) = edge-conf MLP;
// blocks [E, E+NC) = corner scatter-mean + per-corner conv0 GEMM row.
// ---------------------------------------------------------------------------
__global__ void k_edge_corner(const float* __restrict__ W1, const float* __restrict__ b1,
                              const float* __restrict__ W2, const float* __restrict__ b2,
                              const int* __restrict__ pairs,
                              const float* __restrict__ corners,
                              float* __restrict__ out) {
    int t = threadIdx.x;
    if (blockIdx.x < E) {
        int e = blockIdx.x;
        __shared__ float sx[ED];
        __shared__ float sr[64];
        for (int i = t; i < ED; i += 256) sx[i] = g_edge_x[e * ED + i];
        __syncthreads();
        int ks = t & 3, o = t >> 2;
        float acc = 0.f;
        #pragma unroll 16
        for (int i = ks; i < ED; i += 4) acc += sx[i] * W1[o * ED + i];
        acc += __shfl_down_sync(0xFFFFFFFFu, acc, 1);
        acc += __shfl_down_sync(0xFFFFFFFFu, acc, 2);
        if (ks == 0) sr[o] = fmaxf(acc + b1[o], 0.f) * W2[o];
        __syncthreads();
        if (t < 32) {
            float v = sr[t] + sr[t + 32];
            #pragma unroll
            for (int off = 16; off > 0; off >>= 1)
                v += __shfl_xor_sync(0xFFFFFFFFu, v, off);
            if (t == 0) out[OFF_EC + e] = 1.f / (1.f + expf(-(v + b2[0])));
        }
    } else {
        int c = blockIdx.x - E;
        __shared__ unsigned mask[NP / 32];
        __shared__ int sedge[NP];
        __shared__ float sfeat[LIN];
        if (t < NP / 32) mask[t] = 0u;
        __syncthreads();
        #pragma unroll
        for (int k = 0; k < 2; k++) {
            int p = t + k * 256;
            int2 pr = ((const int2*)pairs)[p];
            sedge[p] = pr.y;
            if (pr.x == c) atomicOr(&mask[p >> 5], 1u << (p & 31));
        }
        __syncthreads();
        float sum = 0.f, cnt = 0.f;
        #pragma unroll
        for (int w = 0; w < NP / 32; w++) {
            unsigned m = mask[w];
            while (m) {
                int b = __ffs(m) - 1;
                m &= m - 1;
                sum += g_edge_x[sedge[w * 32 + b] * ED + t];
                cnt += 1.f;
            }
        }
        sfeat[t] = sum / fmaxf(cnt, 1.f);
        if (t < 2) sfeat[ED + t] = corners[c * 2 + t];
        __syncthreads();
        if (t < ZW) {
            float a0 = 0.f, a1 = 0.f, a2 = 0.f, a3 = 0.f;
            int i = 0;
            #pragma unroll 2
            for (; i + 3 < LIN; i += 4) {
                a0 += sfeat[i]     * g_Wt[(i    ) * ZW + t];
                a1 += sfeat[i + 1] * g_Wt[(i + 1) * ZW + t];
                a2 += sfeat[i + 2] * g_Wt[(i + 2) * ZW + t];
                a3 += sfeat[i + 3] * g_Wt[(i + 3) * ZW + t];
            }
            for (; i < LIN; i++) a0 += sfeat[i] * g_Wt[i * ZW + t];
            g_z[c * ZW + t] = (a0 + a1) + (a2 + a3);
        }
    }
}

// ---------------------------------------------------------------------------
// Kernel 3: conv0 assembly + conv1 (wide). grid = (4, NL), 512 threads =
// (ks:4, j:8, o_local:16). 16 iters/thread + shfl reduce.
// ---------------------------------------------------------------------------
__global__ void k_conv1(const int* __restrict__ loops,
                        const float* __restrict__ bc0,
                        const float* __restrict__ Wc1, const float* __restrict__ bc1) {
    int l = blockIdx.y, bo = blockIdx.x, t = threadIdx.x;
    __shared__ int   ci[LL];
    __shared__ float zz[LL * ZPAD];
    __shared__ float hA[64 * LL];
    if (t < LL) ci[t] = loops[l * LL + t];
    __syncthreads();
    for (int idx = t; idx < LL * ZW; idx += 512) {
        int jj = idx / ZW, ok = idx - jj * ZW;
        zz[jj * ZPAD + ok] = g_z[ci[jj] * ZW + ok];
    }
    __syncthreads();
    {   // conv0 assembly
        int o = t >> 3, j = t & 7;
        int jm = j - 1; if (jm < 0) jm = 1;
        int jp = j + 1; if (jp > 7) jp = 6;
        float a = bc0[o] + zz[jm * ZPAD + o * 3]
                         + zz[j  * ZPAD + o * 3 + 1]
                         + zz[jp * ZPAD + o * 3 + 2];
        hA[o * LL + j] = fmaxf(a, 0.f);
    }
    __syncthreads();

    int ks = t & 3, j = (t >> 2) & 7, ol = t >> 5;
    int o = bo * 16 + ol;
    int jm = j - 1; if (jm < 0) jm = 1;
    int jp = j + 1; if (jp > 7) jp = 6;
    float acc = 0.f;
    #pragma unroll
    for (int i = ks; i < 64; i += 4) {
        const float* w = Wc1 + (o * 64 + i) * 3;
        acc += w[0] * hA[i * 8 + jm] + w[1] * hA[i * 8 + j] + w[2] * hA[i * 8 + jp];
    }
    acc += __shfl_down_sync(0xFFFFFFFFu, acc, 1);
    acc += __shfl_down_sync(0xFFFFFFFFu, acc, 2);
    if (ks == 0)
        g_h2[(l * 64 + o) * LL + j] = fmaxf(acc + bc1[o], 0.f);
}

// ---------------------------------------------------------------------------
// Kernel 4: conv2 (wide) with max-over-L fused via warp shuffles.
// grid = (4, NL), 512 threads = (ks:4, j:8, o_local:16).
// ---------------------------------------------------------------------------
__global__ void k_conv2(const float* __restrict__ Wc2, const float* __restrict__ bc2) {
    int l = blockIdx.y, bo = blockIdx.x, t = threadIdx.x;
    __shared__ float hB[64 * LL];
    hB[t] = g_h2[l * 512 + t];
    __syncthreads();

    int ks = t & 3, j = (t >> 2) & 7, ol = t >> 5;
    int o = bo * 16 + ol;
    int jm = j - 1; if (jm < 0) jm = 1;
    int jp = j + 1; if (jp > 7) jp = 6;
    float acc = 0.f;
    #pragma unroll
    for (int i = ks; i < 64; i += 4) {
        const float* w = Wc2 + (o * 64 + i) * 3;
        acc += w[0] * hB[i * 8 + jm] + w[1] * hB[i * 8 + j] + w[2] * hB[i * 8 + jp];
    }
    acc += __shfl_down_sync(0xFFFFFFFFu, acc, 1);
    acc += __shfl_down_sync(0xFFFFFFFFu, acc, 2);
    float v = (ks == 0) ? fmaxf(acc + bc2[o], 0.f) : -FLT_MAX;
    v = fmaxf(v, __shfl_xor_sync(0xFFFFFFFFu, v, 4));
    v = fmaxf(v, __shfl_xor_sync(0xFFFFFFFFu, v, 8));
    v = fmaxf(v, __shfl_xor_sync(0xFFFFFFFFu, v, 16));
    if ((t & 31) == 0) g_loop_feat[l * FEAT + o] = v;
}

// ---------------------------------------------------------------------------
// Kernel 5: loop-conf MLP (tiny). grid = NL, 32 threads, register-resident.
// ---------------------------------------------------------------------------
__global__ void k_loopmlp(const float* __restrict__ Wl1, const float* __restrict__ bl1,
                          const float* __restrict__ Wl2, const float* __restrict__ bl2,
                          float* __restrict__ out) {
    int l = blockIdx.x, t = threadIdx.x;       // 32 threads
    float f0 = g_loop_feat[l * FEAT + t];
    float f1 = g_loop_feat[l * FEAT + 32 + t];
    float a = bl1[t];
    #pragma unroll
    for (int i = 0; i < 32; i++) {
        a += __shfl_sync(0xFFFFFFFFu, f0, i) * Wl1[t * 64 + i];
        a += __shfl_sync(0xFFFFFFFFu, f1, i) * Wl1[t * 64 + 32 + i];
    }
    float v = fmaxf(a, 0.f) * Wl2[t];
    #pragma unroll
    for (int off = 16; off > 0; off >>= 1)
        v += __shfl_xor_sync(0xFFFFFFFFu, v, off);
    if (t == 0) out[OFF_LC + l] = 1.f / (1.f + expf(-(v + bl2[0])));
}

// ---------------------------------------------------------------------------
// Kernel 6: confidence-weighted loop-feature average per edge + final 1x1 conv
// ---------------------------------------------------------------------------
__global__ void k_final(const float* __restrict__ coord,
                        const float* __restrict__ Wagg,
                        float* __restrict__ out) {
    int e = blockIdx.x, t = threadIdx.x;       // 128 threads
    __shared__ float cat[C + FEAT];
    __shared__ float lconf[NL];
    if (t < NL) lconf[t] = out[OFF_LC + t];
    if (t < C)  cat[t]   = coord[e * C + t];
    __syncthreads();
    if (t < FEAT) {
        float num = 0.f, den = 0.f;
        #pragma unroll 8
        for (int l = 0; l < NL; l++) {
            float w = lconf[l] * out[OFF_LE + l * E + e];
            num += w * g_loop_feat[l * FEAT + t];
            den += w;
        }
        cat[C + t] = num / fmaxf(den, 1e-4f);
    }
    __syncthreads();
    float acc = 0.f;
    const float* w = Wagg + t * (C + FEAT);
    #pragma unroll 8
    for (int i = 0; i < C + FEAT; i++) acc += cat[i] * w[i];
    out[e * C + t] = fmaxf(acc, 0.f);
}

// ---------------------------------------------------------------------------
extern "C" void kernel_launch(void* const* d_in, const int* in_sizes, int n_in,
                              void* d_out, int out_size) {
    const float* image_x = (const float*)d_in[0];
    const float* coord_x = (const float*)d_in[1];
    const float* corners = (const float*)d_in[2];
    const int*   pairs   = (const int*)  d_in[3];
    const int*   e_crn   = (const int*)  d_in[4];
    const int*   loops   = (const int*)  d_in[5];
    const float* W_ep1 = (const float*)d_in[6];
    const float* b_ep1 = (const float*)d_in[7];
    const float* W_ep2 = (const float*)d_in[8];
    const float* b_ep2 = (const float*)d_in[9];
    const float* Wc0 = (const float*)d_in[10];
    const float* bc0 = (const float*)d_in[11];
    const float* Wc1 = (const float*)d_in[12];
    const float* bc1 = (const float*)d_in[13];
    const float* Wc2 = (const float*)d_in[14];
    const float* bc2 = (const float*)d_in[15];
    const float* Wl1 = (const float*)d_in[16];
    const float* bl1 = (const float*)d_in[17];
    const float* Wl2 = (const float*)d_in[18];
    const float* bl2 = (const float*)d_in[19];
    const float* Wagg = (const float*)d_in[20];
    float* out = (float*)d_out;

    k_pool_prep  <<<POOLB + NL + 97, 256>>>(image_x, coord_x, loops, e_crn, Wc0, out);
    k_edge_corner<<<E + NC, 256>>>(W_ep1, b_ep1, W_ep2, b_ep2, pairs, corners, out);
    {
        dim3 grid(4, NL);
        k_conv1 <<<grid, 512>>>(loops, bc0, Wc1, bc1);
        k_conv2 <<<grid, 512>>>(Wc2, bc2);
    }
    k_loopmlp    <<<NL, 32>>>(Wl1, bl1, Wl2, bl2, out);
    k_final      <<<E, 128>>>(coord_x, Wagg, out);
}